// round 9
// baseline (speedup 1.0000x reference)
#include <cuda_runtime.h>
#include <cstdint>

#define B_    512
#define HW_   128
#define C1_   32
#define C2_   64

// Padded intermediate h: [512][32][66][68], zero border. Valid data [1..64][1..64].
#define HP_R   66
#define HP_C   68
#define HP_CH  (HP_R * HP_C)          // 4488
__device__ float g_h[(size_t)B_ * C1_ * HP_CH];   // ~294 MB

// Pre-packed conv2 weights: [cc][oc][cil][ky][4], pre-scaled by BN scale.
__device__ float g_w2p[8 * 3072];
// Per-image partial sums from conv2 blocks: [b][8]  (4 tiles x 2 oc-halves)
__device__ float g_part[B_ * 8];

// ---- cp.async helpers -----------------------------------------------------
__device__ __forceinline__ uint32_t sptr(const void* p) {
    return (uint32_t)__cvta_generic_to_shared(p);
}
__device__ __forceinline__ void cpa16(uint32_t dst, const void* src) {
    asm volatile("cp.async.cg.shared.global [%0], [%1], 16;" :: "r"(dst), "l"(src));
}
__device__ __forceinline__ void cpa4(uint32_t dst, const void* src) {
    asm volatile("cp.async.ca.shared.global [%0], [%1], 4;" :: "r"(dst), "l"(src));
}
__device__ __forceinline__ void cpa_commit() {
    asm volatile("cp.async.commit_group;" ::: "memory");
}
template <int N>
__device__ __forceinline__ void cpa_wait() {
    asm volatile("cp.async.wait_group %0;" :: "n"(N) : "memory");
}

// ---------------------------------------------------------------------------
// Kernel 0: pre-pack conv2 weights (18432 items)
// ---------------------------------------------------------------------------
__global__ void conv2_prep(const float* __restrict__ w2,
                           const float* __restrict__ g2,
                           const float* __restrict__ v2)
{
    int i = blockIdx.x * 256 + threadIdx.x;
    if (i >= 8 * C2_ * 36) return;
    int cc  = i / (C2_ * 36);
    int rem = i % (C2_ * 36);
    int oc  = rem / 36;
    int k2  = rem % 36;
    int cil = k2 / 9, k = k2 % 9;
    int ky = k / 3, kx = k % 3;
    float inv = g2[oc] * rsqrtf(v2[oc] + 1e-5f);
    g_w2p[cc * 3072 + oc * 48 + cil * 12 + ky * 4 + kx] =
        w2[oc * (C1_ * 9) + (cc * 4 + cil) * 9 + k] * inv;
}

// ---------------------------------------------------------------------------
// Kernel 1: Conv(3->32, k3, s1, p1) + BN + ReLU + MaxPool2  (direct)
// launch_bounds(256,4): push toward 64 regs -> 32 warps/SM.
// ---------------------------------------------------------------------------
__global__ void __launch_bounds__(256, 4) conv1_fused(
    const float* __restrict__ crops,
    const float* __restrict__ w1, const float* __restrict__ b1,
    const float* __restrict__ g1, const float* __restrict__ be1,
    const float* __restrict__ m1, const float* __restrict__ v1)
{
    __shared__ float s_in[3][34][36];
    __shared__ __align__(16) float s_w[C1_ * 36];  // [oc][ci][ky][4] pre-scaled
    __shared__ float s_scale[C1_], s_bias[C1_];

    const int b   = blockIdx.z;
    const int cx0 = blockIdx.x * 32;
    const int cy0 = blockIdx.y * 32;
    const int t   = threadIdx.x;

    if (t < C1_) {
        float inv = g1[t] * rsqrtf(v1[t] + 1e-5f);
        s_scale[t] = inv;
        s_bias[t]  = be1[t] + (b1[t] - m1[t]) * inv;
    }

    const float* cb = crops + (size_t)b * 3 * HW_ * HW_;
    for (int i = t; i < 3 * 34 * 34; i += 256) {
        int ci = i / (34 * 34);
        int rem = i % (34 * 34);
        int r = rem / 34, c = rem % 34;
        int gr = cy0 - 1 + r, gc = cx0 - 1 + c;
        float v = 0.f;
        if (gr >= 0 && gr < HW_ && gc >= 0 && gc < HW_)
            v = cb[ci * HW_ * HW_ + gr * HW_ + gc];
        s_in[ci][r][c] = v;
    }
    __syncthreads();

    for (int i = t; i < C1_ * 27; i += 256) {
        int oc = i / 27, k = i % 27;
        int ci = k / 9, ky = (k % 9) / 3, kx = k % 3;
        s_w[oc * 36 + ci * 12 + ky * 4 + kx] = w1[i] * s_scale[oc];
    }
    __syncthreads();

    const int px = t & 15, py = t >> 4;

    float p[3][4][4];
#pragma unroll
    for (int ci = 0; ci < 3; ci++)
#pragma unroll
        for (int r = 0; r < 4; r++) {
            float2 a  = *(const float2*)&s_in[ci][2 * py + r][2 * px];
            float2 c2 = *(const float2*)&s_in[ci][2 * py + r][2 * px + 2];
            p[ci][r][0] = a.x;  p[ci][r][1] = a.y;
            p[ci][r][2] = c2.x; p[ci][r][3] = c2.y;
        }

    const int oy = blockIdx.y * 16 + py;
    const int ox = blockIdx.x * 16 + px;
    float* hp = g_h + (size_t)b * C1_ * HP_CH + (oy + 1) * HP_C + (ox + 1);
    const float* wp = s_w;

    for (int oc = 0; oc < C1_; oc++, hp += HP_CH, wp += 36) {
        float a00 = 0.f, a01 = 0.f, a10 = 0.f, a11 = 0.f;
        const float4* w4 = (const float4*)wp;
#pragma unroll
        for (int ci = 0; ci < 3; ci++)
#pragma unroll
            for (int ky = 0; ky < 3; ky++) {
                float4 w = w4[ci * 3 + ky];
                a00 = fmaf(p[ci][ky    ][0], w.x, a00);
                a01 = fmaf(p[ci][ky    ][1], w.x, a01);
                a10 = fmaf(p[ci][ky + 1][0], w.x, a10);
                a11 = fmaf(p[ci][ky + 1][1], w.x, a11);
                a00 = fmaf(p[ci][ky    ][1], w.y, a00);
                a01 = fmaf(p[ci][ky    ][2], w.y, a01);
                a10 = fmaf(p[ci][ky + 1][1], w.y, a10);
                a11 = fmaf(p[ci][ky + 1][2], w.y, a11);
                a00 = fmaf(p[ci][ky    ][2], w.z, a00);
                a01 = fmaf(p[ci][ky    ][3], w.z, a01);
                a10 = fmaf(p[ci][ky + 1][2], w.z, a10);
                a11 = fmaf(p[ci][ky + 1][3], w.z, a11);
            }
        float mv = fmaxf(fmaxf(a00, a01), fmaxf(a10, a11)) + s_bias[oc];
        *hp = fmaxf(mv, 0.f);
    }
}

// ---------------------------------------------------------------------------
// Kernel 2: Conv(32->64, s2) + BN + Sigmoid + MaxPool2, cp.async pipeline.
// oc split across 2 blocks (32 oc each, 8 per thread) -> acc 32 regs,
// ~3 blocks/SM (24 warps). Grid dim3(4, 2, 512): x = (tile_x<<1)|oc_half.
// Stage layout (floats): in 4752 | w 1536 -> STG_F = 6288, 2 stages,
// bias(32) @ 12576, red(8) @ 12608. SMEM = 50464 B.
// ---------------------------------------------------------------------------
#define STG_F        6288
#define STG_W_OFF    4752
#define BI_OFF       12576
#define RED_OFF      12608
#define CONV2_SMEM_BYTES  ((2 * STG_F + 32 + 8) * 4)

__global__ void __launch_bounds__(256, 3) conv2_fused(
    const float* __restrict__ b2, const float* __restrict__ g2,
    const float* __restrict__ be2, const float* __restrict__ m2,
    const float* __restrict__ v2,
    float* __restrict__ feat)
{
    extern __shared__ __align__(16) float sm[];

    const int b  = blockIdx.z;
    const int bx = blockIdx.x >> 1;        // tile x
    const int oh = blockIdx.x & 1;         // oc half: 0 -> oc 0..31, 1 -> 32..63
    const int by = blockIdx.y;
    const int t  = threadIdx.x;

    if (t < 32) {
        int c = oh * 32 + t;
        float inv = g2[c] * rsqrtf(v2[c] + 1e-5f);
        sm[BI_OFF + t] = be2[c] + (b2[c] - m2[c]) * inv;
    }

    const float* hp = g_h + (size_t)b * C1_ * HP_CH + (32 * by) * HP_C + (32 * bx);
    const uint32_t sm_u32 = sptr(sm);

    auto issue = [&](int cc, int p) {
        const uint32_t base = sm_u32 + (uint32_t)(p * STG_F) * 4u;
        for (int i = t; i < 4 * 33 * 9; i += 256) {
            int ch  = i / 297;
            int rem = i - ch * 297;
            int r   = rem / 9;
            int s   = rem - r * 9;
            const float* src = hp + (cc * 4 + ch) * HP_CH + r * HP_C;
            uint32_t dst = base + (uint32_t)((ch * 33 + r) * 36) * 4u;
            if (s < 8) cpa16(dst + 16u * s, src + 4 * s);
            else       cpa4(dst + 128u, src + 32);
        }
        // own oc-half weights: 1536 floats = 384 x 16B
        const float4* ws = (const float4*)(g_w2p + cc * 3072 + oh * 1536);
        const uint32_t wb = base + STG_W_OFF * 4u;
        for (int i = t; i < 384; i += 256)
            cpa16(wb + 16u * i, ws + i);
        cpa_commit();
    };

    const int pix = t & 63, grp = t >> 6;      // grp 0..3 -> 8 oc each
    const int px = pix & 7, py = pix >> 3;

    float acc[8][2][2];
#pragma unroll
    for (int i = 0; i < 8; i++) {
        acc[i][0][0] = 0.f; acc[i][0][1] = 0.f;
        acc[i][1][0] = 0.f; acc[i][1][1] = 0.f;
    }

    issue(0, 0);

    for (int cc = 0; cc < 8; cc++) {
        const int cur = cc & 1;
        if (cc < 7) { issue(cc + 1, cur ^ 1); cpa_wait<1>(); }
        else        { cpa_wait<0>(); }
        __syncthreads();

        const float* sin = sm + cur * STG_F;
        const float* sw  = sin + STG_W_OFF;

#pragma unroll
        for (int cil = 0; cil < 4; cil++) {
            const float* row = sin + (cil * 33 + 4 * py) * 36 + 4 * px;
            float p[5][5];
#pragma unroll
            for (int r = 0; r < 5; r++) {
                float4 v4 = *(const float4*)(row + r * 36);
                p[r][0] = v4.x; p[r][1] = v4.y; p[r][2] = v4.z; p[r][3] = v4.w;
                p[r][4] = row[r * 36 + 4];
            }

#pragma unroll
            for (int oc = 0; oc < 8; oc++) {
                const float4* w4 = (const float4*)(sw + (grp * 8 + oc) * 48 + cil * 12);
#pragma unroll
                for (int ky = 0; ky < 3; ky++) {
                    float4 w = w4[ky];
                    acc[oc][0][0] = fmaf(p[ky    ][0], w.x, acc[oc][0][0]);
                    acc[oc][0][1] = fmaf(p[ky    ][2], w.x, acc[oc][0][1]);
                    acc[oc][1][0] = fmaf(p[ky + 2][0], w.x, acc[oc][1][0]);
                    acc[oc][1][1] = fmaf(p[ky + 2][2], w.x, acc[oc][1][1]);
                    acc[oc][0][0] = fmaf(p[ky    ][1], w.y, acc[oc][0][0]);
                    acc[oc][0][1] = fmaf(p[ky    ][3], w.y, acc[oc][0][1]);
                    acc[oc][1][0] = fmaf(p[ky + 2][1], w.y, acc[oc][1][0]);
                    acc[oc][1][1] = fmaf(p[ky + 2][3], w.y, acc[oc][1][1]);
                    acc[oc][0][0] = fmaf(p[ky    ][2], w.z, acc[oc][0][0]);
                    acc[oc][0][1] = fmaf(p[ky    ][4], w.z, acc[oc][0][1]);
                    acc[oc][1][0] = fmaf(p[ky + 2][2], w.z, acc[oc][1][0]);
                    acc[oc][1][1] = fmaf(p[ky + 2][4], w.z, acc[oc][1][1]);
                }
            }
        }
        __syncthreads();
    }

    // Epilogue: max-pool -> +bias -> sigmoid; accumulate score partial
    const int oy = by * 8 + py, ox = bx * 8 + px;
    float* fb = feat + (size_t)b * C2_ * 16 * 16;
    float lsum = 0.f;
#pragma unroll
    for (int oc = 0; oc < 8; oc++) {
        int cl = grp * 8 + oc;                  // local oc (0..31)
        int c  = oh * 32 + cl;                  // global oc
        float m = fmaxf(fmaxf(acc[oc][0][0], acc[oc][0][1]),
                        fmaxf(acc[oc][1][0], acc[oc][1][1]));
        float v = m + sm[BI_OFF + cl];
        float sig = 1.f / (1.f + __expf(-v));
        fb[c * 256 + oy * 16 + ox] = sig;
        lsum += sig;
    }
#pragma unroll
    for (int o = 16; o > 0; o >>= 1) lsum += __shfl_down_sync(0xffffffffu, lsum, o);
    if ((t & 31) == 0) sm[RED_OFF + (t >> 5)] = lsum;
    __syncthreads();
    if (t < 8) {
        lsum = sm[RED_OFF + t];
#pragma unroll
        for (int o = 4; o > 0; o >>= 1) lsum += __shfl_down_sync(0xffu, lsum, o);
        if (t == 0) g_part[b * 8 + (by * 2 + bx) * 2 + oh] = lsum;
    }
}

// ---------------------------------------------------------------------------
// Kernel 3: final score: sum 8 partials per image -> scores + detected
// ---------------------------------------------------------------------------
__global__ void __launch_bounds__(256) score_final(
    float* __restrict__ scores, float* __restrict__ detected)
{
    int b = blockIdx.x * 256 + threadIdx.x;
    if (b >= B_) return;
    const float4* p = (const float4*)(g_part + b * 8);
    float4 u = p[0], w = p[1];
    float s = ((u.x + u.y) + (u.z + u.w)) + ((w.x + w.y) + (w.z + w.w));
    float sc = s * (1.f / 16384.f);
    scores[b]   = sc;
    detected[b] = (sc >= 0.55f) ? 1.f : 0.f;
}

// ---------------------------------------------------------------------------
extern "C" void kernel_launch(void* const* d_in, const int* in_sizes, int n_in,
                              void* d_out, int out_size)
{
    const float* crops = (const float*)d_in[0];
    const float* w1  = (const float*)d_in[1];
    const float* b1  = (const float*)d_in[2];
    const float* g1  = (const float*)d_in[3];
    const float* be1 = (const float*)d_in[4];
    const float* m1  = (const float*)d_in[5];
    const float* v1  = (const float*)d_in[6];
    const float* w2  = (const float*)d_in[7];
    const float* b2  = (const float*)d_in[8];
    const float* g2  = (const float*)d_in[9];
    const float* be2 = (const float*)d_in[10];
    const float* m2  = (const float*)d_in[11];
    const float* v2  = (const float*)d_in[12];

    float* out      = (float*)d_out;
    float* feat     = out;                                   // 512*64*16*16
    float* scores   = out + (size_t)B_ * C2_ * 16 * 16;      // +512
    float* detected = scores + B_;                           // +512

    static int smem_set = 0;
    if (!smem_set) {
        cudaFuncSetAttribute(conv2_fused,
                             cudaFuncAttributeMaxDynamicSharedMemorySize,
                             CONV2_SMEM_BYTES);
        smem_set = 1;
    }

    conv2_prep<<<72, 256>>>(w2, g2, v2);
    conv1_fused<<<dim3(4, 4, B_), 256>>>(crops, w1, b1, g1, be1, m1, v1);
    conv2_fused<<<dim3(4, 2, B_), 256, CONV2_SMEM_BYTES>>>(b2, g2, be2, m2, v2, feat);
    score_final<<<2, 256>>>(scores, detected);
}

// round 10
// speedup vs baseline: 1.0334x; 1.0334x over previous
#include <cuda_runtime.h>
#include <cstdint>

#define B_    512
#define HW_   128
#define C1_   32
#define C2_   64
#define SLICES 4
#define BSL   (B_ / SLICES)

// Padded intermediate h: [512][32][66][68], zero border. Valid data [1..64][1..64].
#define HP_R   66
#define HP_C   68
#define HP_CH  (HP_R * HP_C)          // 4488
__device__ float g_h[(size_t)B_ * C1_ * HP_CH];   // ~294 MB

// Pre-packed conv2 weights: [cc][oc][cil][ky][4], pre-scaled by BN scale.
__device__ float g_w2p[8 * 3072];
// Per-image partial sums from conv2 blocks: [b][4]
__device__ float g_part[B_ * 4];

// ---- cp.async helpers -----------------------------------------------------
__device__ __forceinline__ uint32_t sptr(const void* p) {
    return (uint32_t)__cvta_generic_to_shared(p);
}
__device__ __forceinline__ void cpa16(uint32_t dst, const void* src) {
    asm volatile("cp.async.cg.shared.global [%0], [%1], 16;" :: "r"(dst), "l"(src));
}
__device__ __forceinline__ void cpa4(uint32_t dst, const void* src) {
    asm volatile("cp.async.ca.shared.global [%0], [%1], 4;" :: "r"(dst), "l"(src));
}
__device__ __forceinline__ void cpa_commit() {
    asm volatile("cp.async.commit_group;" ::: "memory");
}
template <int N>
__device__ __forceinline__ void cpa_wait() {
    asm volatile("cp.async.wait_group %0;" :: "n"(N) : "memory");
}

// ---------------------------------------------------------------------------
// Kernel 0: pre-pack conv2 weights (18432 items)
// ---------------------------------------------------------------------------
__global__ void conv2_prep(const float* __restrict__ w2,
                           const float* __restrict__ g2,
                           const float* __restrict__ v2)
{
    int i = blockIdx.x * 256 + threadIdx.x;
    if (i >= 8 * C2_ * 36) return;
    int cc  = i / (C2_ * 36);
    int rem = i % (C2_ * 36);
    int oc  = rem / 36;
    int k2  = rem % 36;
    int cil = k2 / 9, k = k2 % 9;
    int ky = k / 3, kx = k % 3;
    float inv = g2[oc] * rsqrtf(v2[oc] + 1e-5f);
    g_w2p[cc * 3072 + oc * 48 + cil * 12 + ky * 4 + kx] =
        w2[oc * (C1_ * 9) + (cc * 4 + cil) * 9 + k] * inv;
}

// ---------------------------------------------------------------------------
// Kernel 1: Conv(3->32, k3, s1, p1) + BN + ReLU + MaxPool2  (direct, R8 body)
// ---------------------------------------------------------------------------
__global__ void __launch_bounds__(256) conv1_fused(
    const float* __restrict__ crops,
    const float* __restrict__ w1, const float* __restrict__ b1,
    const float* __restrict__ g1, const float* __restrict__ be1,
    const float* __restrict__ m1, const float* __restrict__ v1,
    int b0)
{
    __shared__ float s_in[3][34][36];
    __shared__ __align__(16) float s_w[C1_ * 36];  // [oc][ci][ky][4] pre-scaled
    __shared__ float s_scale[C1_], s_bias[C1_];

    const int b   = blockIdx.z + b0;
    const int cx0 = blockIdx.x * 32;
    const int cy0 = blockIdx.y * 32;
    const int t   = threadIdx.x;

    if (t < C1_) {
        float inv = g1[t] * rsqrtf(v1[t] + 1e-5f);
        s_scale[t] = inv;
        s_bias[t]  = be1[t] + (b1[t] - m1[t]) * inv;
    }

    const float* cb = crops + (size_t)b * 3 * HW_ * HW_;
    for (int i = t; i < 3 * 34 * 34; i += 256) {
        int ci = i / (34 * 34);
        int rem = i % (34 * 34);
        int r = rem / 34, c = rem % 34;
        int gr = cy0 - 1 + r, gc = cx0 - 1 + c;
        float v = 0.f;
        if (gr >= 0 && gr < HW_ && gc >= 0 && gc < HW_)
            v = cb[ci * HW_ * HW_ + gr * HW_ + gc];
        s_in[ci][r][c] = v;
    }
    __syncthreads();

    for (int i = t; i < C1_ * 27; i += 256) {
        int oc = i / 27, k = i % 27;
        int ci = k / 9, ky = (k % 9) / 3, kx = k % 3;
        s_w[oc * 36 + ci * 12 + ky * 4 + kx] = w1[i] * s_scale[oc];
    }
    __syncthreads();

    const int px = t & 15, py = t >> 4;

    float p[3][4][4];
#pragma unroll
    for (int ci = 0; ci < 3; ci++)
#pragma unroll
        for (int r = 0; r < 4; r++) {
            float2 a  = *(const float2*)&s_in[ci][2 * py + r][2 * px];
            float2 c2 = *(const float2*)&s_in[ci][2 * py + r][2 * px + 2];
            p[ci][r][0] = a.x;  p[ci][r][1] = a.y;
            p[ci][r][2] = c2.x; p[ci][r][3] = c2.y;
        }

    const int oy = blockIdx.y * 16 + py;
    const int ox = blockIdx.x * 16 + px;
    float* hp = g_h + (size_t)b * C1_ * HP_CH + (oy + 1) * HP_C + (ox + 1);
    const float* wp = s_w;

    for (int oc = 0; oc < C1_; oc++, hp += HP_CH, wp += 36) {
        float a00 = 0.f, a01 = 0.f, a10 = 0.f, a11 = 0.f;
        const float4* w4 = (const float4*)wp;
#pragma unroll
        for (int ci = 0; ci < 3; ci++)
#pragma unroll
            for (int ky = 0; ky < 3; ky++) {
                float4 w = w4[ci * 3 + ky];
                a00 = fmaf(p[ci][ky    ][0], w.x, a00);
                a01 = fmaf(p[ci][ky    ][1], w.x, a01);
                a10 = fmaf(p[ci][ky + 1][0], w.x, a10);
                a11 = fmaf(p[ci][ky + 1][1], w.x, a11);
                a00 = fmaf(p[ci][ky    ][1], w.y, a00);
                a01 = fmaf(p[ci][ky    ][2], w.y, a01);
                a10 = fmaf(p[ci][ky + 1][1], w.y, a10);
                a11 = fmaf(p[ci][ky + 1][2], w.y, a11);
                a00 = fmaf(p[ci][ky    ][2], w.z, a00);
                a01 = fmaf(p[ci][ky    ][3], w.z, a01);
                a10 = fmaf(p[ci][ky + 1][2], w.z, a10);
                a11 = fmaf(p[ci][ky + 1][3], w.z, a11);
            }
        float mv = fmaxf(fmaxf(a00, a01), fmaxf(a10, a11)) + s_bias[oc];
        *hp = fmaxf(mv, 0.f);
    }
}

// ---------------------------------------------------------------------------
// Kernel 2: Conv(32->64, s2) + BN + Sigmoid + MaxPool2 (R8 body, cp.async)
// ---------------------------------------------------------------------------
#define STG_F        7824
#define STG_W_OFF    4752
#define BI_OFF       15648
#define RED_OFF      (BI_OFF + 64)
#define CONV2_SMEM_BYTES  ((2 * STG_F + 64 + 8) * 4)

__global__ void __launch_bounds__(256) conv2_fused(
    const float* __restrict__ b2, const float* __restrict__ g2,
    const float* __restrict__ be2, const float* __restrict__ m2,
    const float* __restrict__ v2,
    float* __restrict__ feat, int b0)
{
    extern __shared__ __align__(16) float sm[];

    const int b  = blockIdx.z + b0;
    const int bx = blockIdx.x, by = blockIdx.y;
    const int t  = threadIdx.x;

    if (t < C2_) {
        float inv = g2[t] * rsqrtf(v2[t] + 1e-5f);
        sm[BI_OFF + t] = be2[t] + (b2[t] - m2[t]) * inv;
    }

    const float* hp = g_h + (size_t)b * C1_ * HP_CH + (32 * by) * HP_C + (32 * bx);
    const uint32_t sm_u32 = sptr(sm);

    auto issue = [&](int cc, int p) {
        const uint32_t base = sm_u32 + (uint32_t)(p * STG_F) * 4u;
        for (int i = t; i < 4 * 33 * 9; i += 256) {
            int ch  = i / 297;
            int rem = i - ch * 297;
            int r   = rem / 9;
            int s   = rem - r * 9;
            const float* src = hp + (cc * 4 + ch) * HP_CH + r * HP_C;
            uint32_t dst = base + (uint32_t)((ch * 33 + r) * 36) * 4u;
            if (s < 8) cpa16(dst + 16u * s, src + 4 * s);
            else       cpa4(dst + 128u, src + 32);
        }
        const float4* ws = (const float4*)(g_w2p + cc * 3072);
        const uint32_t wb = base + STG_W_OFF * 4u;
        for (int i = t; i < 768; i += 256)
            cpa16(wb + 16u * i, ws + i);
        cpa_commit();
    };

    const int pix = t & 63, grp = t >> 6;
    const int px = pix & 7, py = pix >> 3;

    float acc[16][2][2];
#pragma unroll
    for (int i = 0; i < 16; i++) {
        acc[i][0][0] = 0.f; acc[i][0][1] = 0.f;
        acc[i][1][0] = 0.f; acc[i][1][1] = 0.f;
    }

    issue(0, 0);

    for (int cc = 0; cc < 8; cc++) {
        const int cur = cc & 1;
        if (cc < 7) { issue(cc + 1, cur ^ 1); cpa_wait<1>(); }
        else        { cpa_wait<0>(); }
        __syncthreads();

        const float* sin = sm + cur * STG_F;
        const float* sw  = sin + STG_W_OFF;

#pragma unroll
        for (int cil = 0; cil < 4; cil++) {
            const float* row = sin + (cil * 33 + 4 * py) * 36 + 4 * px;
            float p[5][5];
#pragma unroll
            for (int r = 0; r < 5; r++) {
                float4 v4 = *(const float4*)(row + r * 36);
                p[r][0] = v4.x; p[r][1] = v4.y; p[r][2] = v4.z; p[r][3] = v4.w;
                p[r][4] = row[r * 36 + 4];
            }

#pragma unroll
            for (int oc = 0; oc < 16; oc++) {
                const float4* w4 = (const float4*)(sw + (grp * 16 + oc) * 48 + cil * 12);
#pragma unroll
                for (int ky = 0; ky < 3; ky++) {
                    float4 w = w4[ky];
                    acc[oc][0][0] = fmaf(p[ky    ][0], w.x, acc[oc][0][0]);
                    acc[oc][0][1] = fmaf(p[ky    ][2], w.x, acc[oc][0][1]);
                    acc[oc][1][0] = fmaf(p[ky + 2][0], w.x, acc[oc][1][0]);
                    acc[oc][1][1] = fmaf(p[ky + 2][2], w.x, acc[oc][1][1]);
                    acc[oc][0][0] = fmaf(p[ky    ][1], w.y, acc[oc][0][0]);
                    acc[oc][0][1] = fmaf(p[ky    ][3], w.y, acc[oc][0][1]);
                    acc[oc][1][0] = fmaf(p[ky + 2][1], w.y, acc[oc][1][0]);
                    acc[oc][1][1] = fmaf(p[ky + 2][3], w.y, acc[oc][1][1]);
                    acc[oc][0][0] = fmaf(p[ky    ][2], w.z, acc[oc][0][0]);
                    acc[oc][0][1] = fmaf(p[ky    ][4], w.z, acc[oc][0][1]);
                    acc[oc][1][0] = fmaf(p[ky + 2][2], w.z, acc[oc][1][0]);
                    acc[oc][1][1] = fmaf(p[ky + 2][4], w.z, acc[oc][1][1]);
                }
            }
        }
        __syncthreads();
    }

    const int oy = by * 8 + py, ox = bx * 8 + px;
    float* fb = feat + (size_t)b * C2_ * 16 * 16;
    float lsum = 0.f;
#pragma unroll
    for (int oc = 0; oc < 16; oc++) {
        int c = grp * 16 + oc;
        float m = fmaxf(fmaxf(acc[oc][0][0], acc[oc][0][1]),
                        fmaxf(acc[oc][1][0], acc[oc][1][1]));
        float v = m + sm[BI_OFF + c];
        float sig = 1.f / (1.f + __expf(-v));
        fb[c * 256 + oy * 16 + ox] = sig;
        lsum += sig;
    }
#pragma unroll
    for (int o = 16; o > 0; o >>= 1) lsum += __shfl_down_sync(0xffffffffu, lsum, o);
    if ((t & 31) == 0) sm[RED_OFF + (t >> 5)] = lsum;
    __syncthreads();
    if (t < 8) {
        lsum = sm[RED_OFF + t];
#pragma unroll
        for (int o = 4; o > 0; o >>= 1) lsum += __shfl_down_sync(0xffu, lsum, o);
        if (t == 0) g_part[b * 4 + by * 2 + bx] = lsum;
    }
}

// ---------------------------------------------------------------------------
// Kernel 3: final score: sum 4 partials per image -> scores + detected
// ---------------------------------------------------------------------------
__global__ void __launch_bounds__(256) score_final(
    float* __restrict__ scores, float* __restrict__ detected)
{
    int b = blockIdx.x * 256 + threadIdx.x;
    if (b >= B_) return;
    const float* p = g_part + b * 4;
    float s = (p[0] + p[1]) + (p[2] + p[3]);
    float sc = s * (1.f / 16384.f);
    scores[b]   = sc;
    detected[b] = (sc >= 0.55f) ? 1.f : 0.f;
}

// ---------------------------------------------------------------------------
extern "C" void kernel_launch(void* const* d_in, const int* in_sizes, int n_in,
                              void* d_out, int out_size)
{
    const float* crops = (const float*)d_in[0];
    const float* w1  = (const float*)d_in[1];
    const float* b1  = (const float*)d_in[2];
    const float* g1  = (const float*)d_in[3];
    const float* be1 = (const float*)d_in[4];
    const float* m1  = (const float*)d_in[5];
    const float* v1  = (const float*)d_in[6];
    const float* w2  = (const float*)d_in[7];
    const float* b2  = (const float*)d_in[8];
    const float* g2  = (const float*)d_in[9];
    const float* be2 = (const float*)d_in[10];
    const float* m2  = (const float*)d_in[11];
    const float* v2  = (const float*)d_in[12];

    float* out      = (float*)d_out;
    float* feat     = out;                                   // 512*64*16*16
    float* scores   = out + (size_t)B_ * C2_ * 16 * 16;      // +512
    float* detected = scores + B_;                           // +512

    static cudaStream_t s2 = nullptr;
    static cudaEvent_t ev1[SLICES], ev2[SLICES];
    static int init_done = 0;
    if (!init_done) {
        cudaFuncSetAttribute(conv2_fused,
                             cudaFuncAttributeMaxDynamicSharedMemorySize,
                             CONV2_SMEM_BYTES);
        cudaStreamCreateWithFlags(&s2, cudaStreamNonBlocking);
        for (int k = 0; k < SLICES; k++) {
            cudaEventCreateWithFlags(&ev1[k], cudaEventDisableTiming);
            cudaEventCreateWithFlags(&ev2[k], cudaEventDisableTiming);
        }
        init_done = 1;
    }

    // Stream 0 (capture stream): prep, then all conv1 slices.
    // Stream s2: conv2 slice k gated on conv1 slice k; rejoins stream 0 at end.
    conv2_prep<<<72, 256>>>(w2, g2, v2);

    for (int k = 0; k < SLICES; k++) {
        conv1_fused<<<dim3(4, 4, BSL), 256>>>(crops, w1, b1, g1, be1, m1, v1,
                                              k * BSL);
        cudaEventRecord(ev1[k], 0);
        cudaStreamWaitEvent(s2, ev1[k], 0);
        conv2_fused<<<dim3(2, 2, BSL), 256, CONV2_SMEM_BYTES, s2>>>(
            b2, g2, be2, m2, v2, feat, k * BSL);
        cudaEventRecord(ev2[k], s2);
    }
    for (int k = 0; k < SLICES; k++)
        cudaStreamWaitEvent(0, ev2[k], 0);

    score_final<<<2, 256>>>(scores, detected);
}

// round 12
// speedup vs baseline: 1.1298x; 1.0933x over previous
#include <cuda_runtime.h>
#include <cstdint>

#define B_    512
#define HW_   128
#define C1_   32
#define C2_   64

// Padded intermediate h: [512][32][66][68], zero border. Valid data [1..64][1..64].
#define HP_R   66
#define HP_C   68
#define HP_CH  (HP_R * HP_C)          // 4488
__device__ float g_h[(size_t)B_ * C1_ * HP_CH];   // ~294 MB

// Pre-packed conv2 weights: [cc][oc][cil][ky][4], pre-scaled by BN scale.
__device__ float g_w2p[8 * 3072];
// Per-image partial sums from conv2 blocks: [b][4]
__device__ float g_part[B_ * 4];

// ---- cp.async helpers -----------------------------------------------------
__device__ __forceinline__ uint32_t sptr(const void* p) {
    return (uint32_t)__cvta_generic_to_shared(p);
}
__device__ __forceinline__ void cpa16(uint32_t dst, const void* src) {
    asm volatile("cp.async.cg.shared.global [%0], [%1], 16;" :: "r"(dst), "l"(src));
}
__device__ __forceinline__ void cpa4(uint32_t dst, const void* src) {
    asm volatile("cp.async.ca.shared.global [%0], [%1], 4;" :: "r"(dst), "l"(src));
}
__device__ __forceinline__ void cpa_commit() {
    asm volatile("cp.async.commit_group;" ::: "memory");
}
template <int N>
__device__ __forceinline__ void cpa_wait() {
    asm volatile("cp.async.wait_group %0;" :: "n"(N) : "memory");
}

// ---------------------------------------------------------------------------
// Kernel 0: pre-pack conv2 weights (18432 items)
// ---------------------------------------------------------------------------
__global__ void conv2_prep(const float* __restrict__ w2,
                           const float* __restrict__ g2,
                           const float* __restrict__ v2)
{
    int i = blockIdx.x * 256 + threadIdx.x;
    if (i >= 8 * C2_ * 36) return;
    int cc  = i / (C2_ * 36);
    int rem = i % (C2_ * 36);
    int oc  = rem / 36;
    int k2  = rem % 36;
    int cil = k2 / 9, k = k2 % 9;
    int ky = k / 3, kx = k % 3;
    float inv = g2[oc] * rsqrtf(v2[oc] + 1e-5f);
    g_w2p[cc * 3072 + oc * 48 + cil * 12 + ky * 4 + kx] =
        w2[oc * (C1_ * 9) + (cc * 4 + cil) * 9 + k] * inv;
}

// ---------------------------------------------------------------------------
// Kernel 1: Conv(3->32, k3, s1, p1) + BN + ReLU + MaxPool2  (direct)
// Grid (2, 4, 512), 256 thr. Each thread: TWO horizontally-adjacent pooled
// pixels, all 32 oc -> weight LDS amortized over 2x FFMA work.
// Block tile: pooled 32(w) x 16(h) -> conv 64x32 -> halo 66x34.
// ---------------------------------------------------------------------------
__global__ void __launch_bounds__(256) conv1_fused(
    const float* __restrict__ crops,
    const float* __restrict__ w1, const float* __restrict__ b1,
    const float* __restrict__ g1, const float* __restrict__ be1,
    const float* __restrict__ m1, const float* __restrict__ v1)
{
    __shared__ float s_in[3][34][68];              // 27.7 KB, 16B-friendly stride
    __shared__ __align__(16) float s_w[C1_ * 36];  // [oc][ci][ky][4] pre-scaled
    __shared__ float s_bias[C1_];

    const int b   = blockIdx.z;
    const int cx0 = blockIdx.x * 64;               // conv-col origin
    const int cy0 = blockIdx.y * 32;               // conv-row origin
    const int t   = threadIdx.x;

    if (t < C1_) {
        float inv = g1[t] * rsqrtf(v1[t] + 1e-5f);
        s_bias[t] = be1[t] + (b1[t] - m1[t]) * inv;
    }
    // weights: inv computed inline -> no barrier needed before this fill
    for (int i = t; i < C1_ * 27; i += 256) {
        int oc = i / 27, k = i % 27;
        int ci = k / 9, ky = (k % 9) / 3, kx = k % 3;
        float inv = g1[oc] * rsqrtf(v1[oc] + 1e-5f);
        s_w[oc * 36 + ci * 12 + ky * 4 + kx] = w1[i] * inv;
    }

    const float* cb = crops + (size_t)b * 3 * HW_ * HW_;
    for (int i = t; i < 3 * 34 * 66; i += 256) {
        int ci = i / (34 * 66);
        int rem = i % (34 * 66);
        int r = rem / 66, c = rem % 66;
        int gr = cy0 - 1 + r, gc = cx0 - 1 + c;
        float v = 0.f;
        if (gr >= 0 && gr < HW_ && gc >= 0 && gc < HW_)
            v = cb[ci * HW_ * HW_ + gr * HW_ + gc];
        s_in[ci][r][c] = v;
    }
    __syncthreads();

    const int q  = t & 15;          // pooled col-pair index (covers 2q, 2q+1)
    const int py = t >> 4;          // pooled row in tile (0..15)

    // Patch: 3 ci x 4 rows x 6 cols (conv-window cols 4q..4q+5)
    float p[3][4][6];
#pragma unroll
    for (int ci = 0; ci < 3; ci++)
#pragma unroll
        for (int r = 0; r < 4; r++) {
            const float* row = &s_in[ci][2 * py + r][4 * q];
            float4 v4 = *(const float4*)row;       // 16B aligned (4q, stride 68)
            float2 v2 = *(const float2*)(row + 4);
            p[ci][r][0] = v4.x; p[ci][r][1] = v4.y; p[ci][r][2] = v4.z;
            p[ci][r][3] = v4.w; p[ci][r][4] = v2.x; p[ci][r][5] = v2.y;
        }

    const int oy = blockIdx.y * 16 + py;
    const int ox = blockIdx.x * 32 + 2 * q;        // first pooled col
    float* hp = g_h + (size_t)b * C1_ * HP_CH + (oy + 1) * HP_C + (ox + 1);
    const float* wp = s_w;

    for (int oc = 0; oc < C1_; oc++, hp += HP_CH, wp += 36) {
        // quad A: conv cols 0,1 (patch idx kx, kx+1); quad B: cols 2,3 (kx+2, kx+3)
        float a00 = 0.f, a01 = 0.f, a10 = 0.f, a11 = 0.f;
        float c00 = 0.f, c01 = 0.f, c10 = 0.f, c11 = 0.f;
        const float4* w4 = (const float4*)wp;
#pragma unroll
        for (int ci = 0; ci < 3; ci++)
#pragma unroll
            for (int ky = 0; ky < 3; ky++) {
                float4 w = w4[ci * 3 + ky];
                const float* r0 = p[ci][ky];
                const float* r1 = p[ci][ky + 1];
                a00 = fmaf(r0[0], w.x, a00);  a01 = fmaf(r0[1], w.x, a01);
                a10 = fmaf(r1[0], w.x, a10);  a11 = fmaf(r1[1], w.x, a11);
                c00 = fmaf(r0[2], w.x, c00);  c01 = fmaf(r0[3], w.x, c01);
                c10 = fmaf(r1[2], w.x, c10);  c11 = fmaf(r1[3], w.x, c11);
                a00 = fmaf(r0[1], w.y, a00);  a01 = fmaf(r0[2], w.y, a01);
                a10 = fmaf(r1[1], w.y, a10);  a11 = fmaf(r1[2], w.y, a11);
                c00 = fmaf(r0[3], w.y, c00);  c01 = fmaf(r0[4], w.y, c01);
                c10 = fmaf(r1[3], w.y, c10);  c11 = fmaf(r1[4], w.y, c11);
                a00 = fmaf(r0[2], w.z, a00);  a01 = fmaf(r0[3], w.z, a01);
                a10 = fmaf(r1[2], w.z, a10);  a11 = fmaf(r1[3], w.z, a11);
                c00 = fmaf(r0[4], w.z, c00);  c01 = fmaf(r0[5], w.z, c01);
                c10 = fmaf(r1[4], w.z, c10);  c11 = fmaf(r1[5], w.z, c11);
            }
        float bi = s_bias[oc];
        float mA = fmaxf(fmaxf(a00, a01), fmaxf(a10, a11)) + bi;
        float mB = fmaxf(fmaxf(c00, c01), fmaxf(c10, c11)) + bi;
        hp[0] = fmaxf(mA, 0.f);
        hp[1] = fmaxf(mB, 0.f);
    }
}

// ---------------------------------------------------------------------------
// Kernel 2: Conv(32->64, s2) + BN + Sigmoid + MaxPool2 (R8 body, cp.async)
// ---------------------------------------------------------------------------
#define STG_F        7824
#define STG_W_OFF    4752
#define BI_OFF       15648
#define RED_OFF      (BI_OFF + 64)
#define CONV2_SMEM_BYTES  ((2 * STG_F + 64 + 8) * 4)

__global__ void __launch_bounds__(256) conv2_fused(
    const float* __restrict__ b2, const float* __restrict__ g2,
    const float* __restrict__ be2, const float* __restrict__ m2,
    const float* __restrict__ v2,
    float* __restrict__ feat)
{
    extern __shared__ __align__(16) float sm[];

    const int b  = blockIdx.z;
    const int bx = blockIdx.x, by = blockIdx.y;
    const int t  = threadIdx.x;

    if (t < C2_) {
        float inv = g2[t] * rsqrtf(v2[t] + 1e-5f);
        sm[BI_OFF + t] = be2[t] + (b2[t] - m2[t]) * inv;
    }

    const float* hp = g_h + (size_t)b * C1_ * HP_CH + (32 * by) * HP_C + (32 * bx);
    const uint32_t sm_u32 = sptr(sm);

    auto issue = [&](int cc, int p) {
        const uint32_t base = sm_u32 + (uint32_t)(p * STG_F) * 4u;
        for (int i = t; i < 4 * 33 * 9; i += 256) {
            int ch  = i / 297;
            int rem = i - ch * 297;
            int r   = rem / 9;
            int s   = rem - r * 9;
            const float* src = hp + (cc * 4 + ch) * HP_CH + r * HP_C;
            uint32_t dst = base + (uint32_t)((ch * 33 + r) * 36) * 4u;
            if (s < 8) cpa16(dst + 16u * s, src + 4 * s);
            else       cpa4(dst + 128u, src + 32);
        }
        const float4* ws = (const float4*)(g_w2p + cc * 3072);
        const uint32_t wb = base + STG_W_OFF * 4u;
        for (int i = t; i < 768; i += 256)
            cpa16(wb + 16u * i, ws + i);
        cpa_commit();
    };

    const int pix = t & 63, grp = t >> 6;
    const int px = pix & 7, py = pix >> 3;

    float acc[16][2][2];
#pragma unroll
    for (int i = 0; i < 16; i++) {
        acc[i][0][0] = 0.f; acc[i][0][1] = 0.f;
        acc[i][1][0] = 0.f; acc[i][1][1] = 0.f;
    }

    issue(0, 0);

    for (int cc = 0; cc < 8; cc++) {
        const int cur = cc & 1;
        if (cc < 7) { issue(cc + 1, cur ^ 1); cpa_wait<1>(); }
        else        { cpa_wait<0>(); }
        __syncthreads();

        const float* sin = sm + cur * STG_F;
        const float* sw  = sin + STG_W_OFF;

#pragma unroll
        for (int cil = 0; cil < 4; cil++) {
            const float* row = sin + (cil * 33 + 4 * py) * 36 + 4 * px;
            float p[5][5];
#pragma unroll
            for (int r = 0; r < 5; r++) {
                float4 v4 = *(const float4*)(row + r * 36);
                p[r][0] = v4.x; p[r][1] = v4.y; p[r][2] = v4.z; p[r][3] = v4.w;
                p[r][4] = row[r * 36 + 4];
            }

#pragma unroll
            for (int oc = 0; oc < 16; oc++) {
                const float4* w4 = (const float4*)(sw + (grp * 16 + oc) * 48 + cil * 12);
#pragma unroll
                for (int ky = 0; ky < 3; ky++) {
                    float4 w = w4[ky];
                    acc[oc][0][0] = fmaf(p[ky    ][0], w.x, acc[oc][0][0]);
                    acc[oc][0][1] = fmaf(p[ky    ][2], w.x, acc[oc][0][1]);
                    acc[oc][1][0] = fmaf(p[ky + 2][0], w.x, acc[oc][1][0]);
                    acc[oc][1][1] = fmaf(p[ky + 2][2], w.x, acc[oc][1][1]);
                    acc[oc][0][0] = fmaf(p[ky    ][1], w.y, acc[oc][0][0]);
                    acc[oc][0][1] = fmaf(p[ky    ][3], w.y, acc[oc][0][1]);
                    acc[oc][1][0] = fmaf(p[ky + 2][1], w.y, acc[oc][1][0]);
                    acc[oc][1][1] = fmaf(p[ky + 2][3], w.y, acc[oc][1][1]);
                    acc[oc][0][0] = fmaf(p[ky    ][2], w.z, acc[oc][0][0]);
                    acc[oc][0][1] = fmaf(p[ky    ][4], w.z, acc[oc][0][1]);
                    acc[oc][1][0] = fmaf(p[ky + 2][2], w.z, acc[oc][1][0]);
                    acc[oc][1][1] = fmaf(p[ky + 2][4], w.z, acc[oc][1][1]);
                }
            }
        }
        __syncthreads();
    }

    const int oy = by * 8 + py, ox = bx * 8 + px;
    float* fb = feat + (size_t)b * C2_ * 16 * 16;
    float lsum = 0.f;
#pragma unroll
    for (int oc = 0; oc < 16; oc++) {
        int c = grp * 16 + oc;
        float m = fmaxf(fmaxf(acc[oc][0][0], acc[oc][0][1]),
                        fmaxf(acc[oc][1][0], acc[oc][1][1]));
        float v = m + sm[BI_OFF + c];
        float sig = 1.f / (1.f + __expf(-v));
        fb[c * 256 + oy * 16 + ox] = sig;
        lsum += sig;
    }
#pragma unroll
    for (int o = 16; o > 0; o >>= 1) lsum += __shfl_down_sync(0xffffffffu, lsum, o);
    if ((t & 31) == 0) sm[RED_OFF + (t >> 5)] = lsum;
    __syncthreads();
    if (t < 8) {
        lsum = sm[RED_OFF + t];
#pragma unroll
        for (int o = 4; o > 0; o >>= 1) lsum += __shfl_down_sync(0xffu, lsum, o);
        if (t == 0) g_part[b * 4 + by * 2 + bx] = lsum;
    }
}

// ---------------------------------------------------------------------------
// Kernel 3: final score: sum 4 partials per image -> scores + detected
// ---------------------------------------------------------------------------
__global__ void __launch_bounds__(256) score_final(
    float* __restrict__ scores, float* __restrict__ detected)
{
    int b = blockIdx.x * 256 + threadIdx.x;
    if (b >= B_) return;
    const float* p = g_part + b * 4;
    float s = (p[0] + p[1]) + (p[2] + p[3]);
    float sc = s * (1.f / 16384.f);
    scores[b]   = sc;
    detected[b] = (sc >= 0.55f) ? 1.f : 0.f;
}

// ---------------------------------------------------------------------------
extern "C" void kernel_launch(void* const* d_in, const int* in_sizes, int n_in,
                              void* d_out, int out_size)
{
    const float* crops = (const float*)d_in[0];
    const float* w1  = (const float*)d_in[1];
    const float* b1  = (const float*)d_in[2];
    const float* g1  = (const float*)d_in[3];
    const float* be1 = (const float*)d_in[4];
    const float* m1  = (const float*)d_in[5];
    const float* v1  = (const float*)d_in[6];
    const float* w2  = (const float*)d_in[7];
    const float* b2  = (const float*)d_in[8];
    const float* g2  = (const float*)d_in[9];
    const float* be2 = (const float*)d_in[10];
    const float* m2  = (const float*)d_in[11];
    const float* v2  = (const float*)d_in[12];

    float* out      = (float*)d_out;
    float* feat     = out;                                   // 512*64*16*16
    float* scores   = out + (size_t)B_ * C2_ * 16 * 16;      // +512
    float* detected = scores + B_;                           // +512

    static int smem_set = 0;
    if (!smem_set) {
        cudaFuncSetAttribute(conv2_fused,
                             cudaFuncAttributeMaxDynamicSharedMemorySize,
                             CONV2_SMEM_BYTES);
        smem_set = 1;
    }

    conv2_prep<<<72, 256>>>(w2, g2, v2);
    conv1_fused<<<dim3(2, 4, B_), 256>>>(crops, w1, b1, g1, be1, m1, v1);
    conv2_fused<<<dim3(2, 2, B_), 256, CONV2_SMEM_BYTES>>>(b2, g2, be2, m2, v2, feat);
    score_final<<<2, 256>>>(scores, detected);
}